// round 15
// baseline (speedup 1.0000x reference)
#include <cuda_runtime.h>
#include <cstdint>

#define TT  128
#define BB  1024
#define DIN 128
#define HH  256
#define G3  768   // 3*H gate columns (gate-planar-24 layout)

// ---------------- device scratch (static globals; no allocations) ----------
__device__ __align__(16) uint32_t g_Wx0t[G3 * DIN];  // tf32 bits, permuted cols
__device__ __align__(16) uint32_t g_Wh0t[G3 * HH];
__device__ __align__(16) uint32_t g_Wx1t[G3 * HH];
__device__ __align__(16) uint32_t g_Wh1t[G3 * HH];
__device__ float g_bx0p[G3];
__device__ float g_bh0p[G3];
__device__ float g_bx1p[G3];
__device__ float g_bh1p[G3];
__device__ __align__(16) float g_out0[(size_t)TT * BB * HH];  // layer-0 outputs
__device__ __align__(16) float g_hbuf[2][BB * HH];            // dbl-buffered h
__device__ int          g_cntg[16];
__device__ volatile int g_geng[16];

// ---------------- helpers ---------------------------------------------------
__device__ __forceinline__ float sigm_f(float x) {
    return __fdividef(1.0f, 1.0f + __expf(-x));
}
__device__ __forceinline__ float tanh_f(float x) {
    x = fminf(fmaxf(x, -15.0f), 15.0f);
    float e = __expf(-2.0f * x);
    return __fdividef(1.0f - e, 1.0f + e);
}
__device__ __forceinline__ uint32_t cvt_tf32(float f) {
    uint32_t u; asm("cvt.rna.tf32.f32 %0, %1;" : "=r"(u) : "f"(f)); return u;
}
__device__ __forceinline__ void mma_tf32(float* d, const uint32_t* a, const uint32_t* b) {
    asm volatile(
        "mma.sync.aligned.m16n8k8.row.col.f32.tf32.tf32.f32 "
        "{%0,%1,%2,%3}, {%4,%5,%6,%7}, {%8,%9}, {%0,%1,%2,%3};"
        : "+f"(d[0]), "+f"(d[1]), "+f"(d[2]), "+f"(d[3])
        : "r"(a[0]), "r"(a[1]), "r"(a[2]), "r"(a[3]), "r"(b[0]), "r"(b[1]));
}

// 8-CTA group barrier (per batch-group), generation counter survives replays
__device__ __forceinline__ void group_sync(int grp) {
    __syncthreads();
    if (threadIdx.x == 0) {
        __threadfence();
        int gen = g_geng[grp];
        if (atomicAdd(&g_cntg[grp], 1) == 7) {
            g_cntg[grp] = 0;
            __threadfence();
            g_geng[grp] = gen + 1;
        } else {
            while (g_geng[grp] == gen) { __nanosleep(32); }
            __threadfence();
        }
    }
    __syncthreads();
}

// ---------------- weight reordering: gate-planar-24 layout -----------------
// col n in [0,768): block b24=n/24, w=n%24, gate=w/8, unit j=8*b24+(w%8).
// Original row R = gate*HH + j.  All weights -> tf32 bits.
__global__ void reorder_kernel(const float* __restrict__ Wx0, const float* __restrict__ bx0,
                               const float* __restrict__ Wh0, const float* __restrict__ bh0,
                               const float* __restrict__ Wx1, const float* __restrict__ bx1,
                               const float* __restrict__ Wh1, const float* __restrict__ bh1) {
    int tid = blockIdx.x * blockDim.x + threadIdx.x;
    int stride = gridDim.x * blockDim.x;
    for (int idx = tid; idx < G3 * DIN; idx += stride) {
        int n = idx / DIN, k = idx % DIN;
        int w = n % 24;
        int R = (w / 8) * HH + 8 * (n / 24) + (w % 8);
        g_Wx0t[idx] = cvt_tf32(Wx0[R * DIN + k]);
    }
    for (int idx = tid; idx < G3 * HH; idx += stride) {
        int n = idx / HH, k = idx % HH;
        int w = n % 24;
        int R = (w / 8) * HH + 8 * (n / 24) + (w % 8);
        int s = R * HH + k;
        g_Wh0t[idx] = cvt_tf32(Wh0[s]);
        g_Wx1t[idx] = cvt_tf32(Wx1[s]);
        g_Wh1t[idx] = cvt_tf32(Wh1[s]);
    }
    for (int idx = tid; idx < G3; idx += stride) {
        int w = idx % 24;
        int R = (w / 8) * HH + 8 * (idx / 24) + (w % 8);
        g_bx0p[idx] = bx0[R];
        g_bh0p[idx] = bh0[R];
        g_bx1p[idx] = bx1[R];
        g_bh1p[idx] = bh1[R];
    }
}

// ---------------- fused persistent recurrent kernel ------------------------
// Grid 8x16 = 128 CTAs, 256 threads.  CTA (cx, by): 96 gate cols (= 32 hidden
// units, gate-planar), 64 batch rows.  Per step: chunked x-GEMM (A = Xin[t])
// + chunked h-GEMM (A = hbuf), gates computed in registers from fragments.
#define FWS 260   // weight smem stride (≡4 mod 32: (4g+t) banks distinct)
#define FAS 100   // A-chunk stride (96 cols max, ≡4 mod 32)
#define SMEM_F ((2 * 96 * FWS + 64 * FAS) * 4)   // 225280 B

template<int N4, bool LDCV>
__device__ __forceinline__ void fill_tile(uint32_t* As, const float* src,
                                          int ldsrc, int tid) {
    // 64 rows x N4 float4 columns
#pragma unroll
    for (int p = 0; p < (64 * N4) / 256; p++) {
        int idx = p * 256 + tid;
        int row = idx / N4;
        int c4 = (idx - row * N4) * 4;
        const float4* sp = (const float4*)&src[(size_t)row * ldsrc + c4];
        float4 v = LDCV ? __ldcv(sp) : *sp;
        uint4 cv;
        cv.x = cvt_tf32(v.x); cv.y = cvt_tf32(v.y);
        cv.z = cvt_tf32(v.z); cv.w = cvt_tf32(v.w);
        *(uint4*)&As[row * FAS + c4] = cv;
    }
}

__device__ __forceinline__ void gemm_chunk(float acc[2][3][4], const uint32_t* As,
                                           const uint32_t* Ws, int kc, int cw,
                                           int warp_m, int warp_n, int g, int t) {
    for (int ks = 0; ks < (cw >> 3); ks++) {
        int k0 = ks * 8;
        uint32_t a[2][4], b[3][2];
#pragma unroll
        for (int mt = 0; mt < 2; mt++) {
            int r0 = warp_m * 32 + mt * 16;
            a[mt][0] = As[(r0 + g) * FAS + k0 + t];
            a[mt][1] = As[(r0 + g + 8) * FAS + k0 + t];
            a[mt][2] = As[(r0 + g) * FAS + k0 + t + 4];
            a[mt][3] = As[(r0 + g + 8) * FAS + k0 + t + 4];
        }
#pragma unroll
        for (int nt = 0; nt < 3; nt++) {
            int cb = warp_n * 24 + nt * 8;
            b[nt][0] = Ws[(cb + g) * FWS + kc + k0 + t];
            b[nt][1] = Ws[(cb + g) * FWS + kc + k0 + t + 4];
        }
#pragma unroll
        for (int mt = 0; mt < 2; mt++)
#pragma unroll
            for (int nt = 0; nt < 3; nt++)
                mma_tf32(acc[mt][nt], a[mt], b[nt]);
    }
}

__global__ __launch_bounds__(256) void fused_rec(
    const float* __restrict__ Xin, int Kx,
    const uint32_t* __restrict__ Wxt, const uint32_t* __restrict__ Wht,
    const float* __restrict__ bxp, const float* __restrict__ bhp,
    const float* __restrict__ h0,
    const float* __restrict__ gamma, const float* __restrict__ beta,
    float* __restrict__ out_seq, float* __restrict__ final_h) {
    extern __shared__ uint32_t smf[];
    uint32_t* Wxs = smf;                 // [96][FWS]
    uint32_t* Whs = smf + 96 * FWS;      // [96][FWS]
    uint32_t* As  = smf + 2 * 96 * FWS;  // [64][FAS]

    const int tid = threadIdx.x;
    const int wid = tid >> 5, lane = tid & 31;
    const int g = lane >> 2, t = lane & 3;
    const int warp_m = wid & 1, warp_n = wid >> 1;
    const int n0 = blockIdx.x * 96;      // gate-col base
    const int jb = blockIdx.x * 32;      // hidden-unit base
    const int b0 = blockIdx.y * 64;      // batch base
    const int grp = blockIdx.y;

    // one-time weight fill (already tf32 bits)
    const int ksh = (Kx == 128) ? 7 : 8;
    for (int idx = tid; idx < 96 * Kx; idx += 256) {
        int n = idx >> ksh, k = idx & (Kx - 1);
        Wxs[n * FWS + k] = Wxt[(size_t)(n0 + n) * Kx + k];
    }
    for (int idx = tid; idx < 96 * 256; idx += 256) {
        int n = idx >> 8, k = idx & 255;
        Whs[n * FWS + k] = Wht[(size_t)(n0 + n) * HH + k];
    }

    // per-thread constants
    float bx_[3][2], bh_[3][2];
#pragma unroll
    for (int nt = 0; nt < 3; nt++)
#pragma unroll
        for (int u = 0; u < 2; u++) {
            int col = n0 + warp_n * 24 + nt * 8 + 2 * t + u;
            bx_[nt][u] = bxp[col];
            bh_[nt][u] = bhp[col];
        }
    const int jc = jb + warp_n * 8 + 2 * t;
    float gm[4][2], bt[4][2], h_prev[4][2];
#pragma unroll
    for (int i = 0; i < 4; i++) {
        int b = b0 + warp_m * 32 + (i >> 1) * 16 + g + (i & 1) * 8;
#pragma unroll
        for (int u = 0; u < 2; u++) {
            gm[i][u] = gamma[b * HH + jc + u];
            bt[i][u] = beta [b * HH + jc + u];
            h_prev[i][u] = h0[b * HH + jc + u];
        }
    }

    // init hidden state region (64 rows x 32 units)
    for (int idx = tid; idx < 64 * 32; idx += 256) {
        int row = idx >> 5, u = idx & 31;
        int off = (b0 + row) * HH + jb + u;
        g_hbuf[0][off] = h0[off];
    }
    group_sync(grp);

    for (int step = 0; step < TT; step++) {
        const float* hcur = g_hbuf[step & 1];
        float* hnext = g_hbuf[(step + 1) & 1];

        float ax[2][3][4], ah[2][3][4];
#pragma unroll
        for (int mt = 0; mt < 2; mt++)
#pragma unroll
            for (int nt = 0; nt < 3; nt++)
#pragma unroll
                for (int r = 0; r < 4; r++) { ax[mt][nt][r] = 0.0f; ah[mt][nt][r] = 0.0f; }

        // ---- x-GEMM: A = Xin[step] tile (chunked) ----
        const float* xrow = Xin + ((size_t)step * BB + b0) * Kx;
        for (int kc = 0; kc < Kx; kc += 96) {
            int cw = Kx - kc; if (cw > 96) cw = 96;
            __syncthreads();
            if (cw == 96)      fill_tile<24, false>(As, xrow + kc, Kx, tid);
            else if (cw == 64) fill_tile<16, false>(As, xrow + kc, Kx, tid);
            else               fill_tile<8,  false>(As, xrow + kc, Kx, tid);
            __syncthreads();
            gemm_chunk(ax, As, Wxs, kc, cw, warp_m, warp_n, g, t);
        }

        // ---- h-GEMM: A = hcur tile (chunked, ldcv: cross-SM) ----
        const float* hrow = hcur + (size_t)b0 * HH;
        for (int kc = 0; kc < HH; kc += 96) {
            int cw = HH - kc; if (cw > 96) cw = 96;
            __syncthreads();
            if (cw == 96)      fill_tile<24, true>(As, hrow + kc, HH, tid);
            else if (cw == 64) fill_tile<16, true>(As, hrow + kc, HH, tid);
            else               fill_tile<8,  true>(As, hrow + kc, HH, tid);
            __syncthreads();
            gemm_chunk(ah, As, Whs, kc, cw, warp_m, warp_n, g, t);
        }

        // ---- gates + FiLM entirely in registers ----
#pragma unroll
        for (int mt = 0; mt < 2; mt++)
#pragma unroll
            for (int rh = 0; rh < 2; rh++) {
                int i = mt * 2 + rh;
                int b = b0 + warp_m * 32 + mt * 16 + g + rh * 8;
                float hv[2];
#pragma unroll
                for (int u = 0; u < 2; u++) {
                    int rg = 2 * rh + u;
                    float z  = sigm_f(ax[mt][0][rg] + bx_[0][u] + ah[mt][0][rg] + bh_[0][u]);
                    float rr = sigm_f(ax[mt][1][rg] + bx_[1][u] + ah[mt][1][rg] + bh_[1][u]);
                    float nn = tanh_f(ax[mt][2][rg] + bx_[2][u] + rr * (ah[mt][2][rg] + bh_[2][u]));
                    float hp = h_prev[i][u];
                    float h  = nn + z * (hp - nn);
                    hv[u] = fmaf(gm[i][u], h, bt[i][u]);
                    h_prev[i][u] = hv[u];
                }
                float2 hv2 = make_float2(hv[0], hv[1]);
                *(float2*)&hnext[(size_t)b * HH + jc] = hv2;
                *(float2*)&out_seq[((size_t)step * BB + b) * HH + jc] = hv2;
                if (step == TT - 1)
                    *(float2*)&final_h[(size_t)b * HH + jc] = hv2;
            }
        group_sync(grp);
    }
}

// ---------------- host launcher -------------------------------------------
extern "C" void kernel_launch(void* const* d_in, const int* in_sizes, int n_in,
                              void* d_out, int out_size) {
    (void)in_sizes; (void)n_in; (void)out_size;
    const float* x      = (const float*)d_in[0];
    const float* init_s = (const float*)d_in[1];
    const float* gammas = (const float*)d_in[2];
    const float* betas  = (const float*)d_in[3];
    const float* Wx0 = (const float*)d_in[4];
    const float* bx0 = (const float*)d_in[5];
    const float* Wh0 = (const float*)d_in[6];
    const float* bh0 = (const float*)d_in[7];
    const float* Wx1 = (const float*)d_in[8];
    const float* bx1 = (const float*)d_in[9];
    const float* Wh1 = (const float*)d_in[10];
    const float* bh1 = (const float*)d_in[11];
    float* out = (float*)d_out;

    uint32_t *pWx0t, *pWh0t, *pWx1t, *pWh1t;
    float *pbx0p, *pbh0p, *pbx1p, *pbh1p, *pout0;
    cudaGetSymbolAddress((void**)&pWx0t, g_Wx0t);
    cudaGetSymbolAddress((void**)&pWh0t, g_Wh0t);
    cudaGetSymbolAddress((void**)&pWx1t, g_Wx1t);
    cudaGetSymbolAddress((void**)&pWh1t, g_Wh1t);
    cudaGetSymbolAddress((void**)&pbx0p, g_bx0p);
    cudaGetSymbolAddress((void**)&pbh0p, g_bh0p);
    cudaGetSymbolAddress((void**)&pbx1p, g_bx1p);
    cudaGetSymbolAddress((void**)&pbh1p, g_bh1p);
    cudaGetSymbolAddress((void**)&pout0, g_out0);

    cudaFuncSetAttribute(fused_rec,
                         cudaFuncAttributeMaxDynamicSharedMemorySize, SMEM_F);

    const size_t out1_elems = (size_t)TT * BB * HH;

    reorder_kernel<<<768, 256>>>(Wx0, bx0, Wh0, bh0, Wx1, bx1, Wh1, bh1);

    // layer 0: x-projection (K=128) fused with recurrence
    fused_rec<<<dim3(8, 16), 256, SMEM_F>>>(
        x, DIN, pWx0t, pWh0t, pbx0p, pbh0p,
        init_s, gammas, betas,
        pout0, out + out1_elems);

    // layer 1: x-projection (K=256, A = out0) fused with recurrence
    fused_rec<<<dim3(8, 16), 256, SMEM_F>>>(
        pout0, HH, pWx1t, pWh1t, pbx1p, pbh1p,
        init_s + BB * HH, gammas + (size_t)BB * HH, betas + (size_t)BB * HH,
        out, out + out1_elems + (size_t)BB * HH);
}

// round 17
// speedup vs baseline: 1.1728x; 1.1728x over previous
#include <cuda_runtime.h>
#include <cstdint>

#define TT  128
#define BB  1024
#define DIN 128
#define HH  256
#define G3  768   // 3*H, gate-interleaved columns

// ---------------- device scratch (static globals; no allocations) ----------
__device__ __align__(16) uint32_t g_Wx0t[G3 * DIN];  // tf32 bits, [col][k]
__device__ __align__(16) uint32_t g_Wx1t[G3 * HH];
__device__ __align__(16) float g_Wh0p[G3 * HH];
__device__ __align__(16) float g_Wh1p[G3 * HH];
__device__ float g_bx0p[G3];
__device__ float g_bh0p[G3];
__device__ float g_bx1p[G3];
__device__ float g_bh1p[G3];
__device__ __align__(16) float g_xg[(size_t)TT * BB * G3];    // x-gates fp32
__device__ __align__(16) float g_out0[(size_t)TT * BB * HH];  // layer-0 outputs
__device__ __align__(16) float g_hbuf[2][BB * HH];            // dbl-buffered h
__device__ int          g_cntg[16];
__device__ volatile int g_geng[16];

// ---------------- helpers ---------------------------------------------------
__device__ __forceinline__ float sigm_f(float x) {
    return __fdividef(1.0f, 1.0f + __expf(-x));
}
__device__ __forceinline__ float tanh_f(float x) {
    x = fminf(fmaxf(x, -15.0f), 15.0f);
    float e = __expf(-2.0f * x);
    return __fdividef(1.0f - e, 1.0f + e);
}
__device__ __forceinline__ uint32_t cvt_tf32(float f) {
    uint32_t u; asm("cvt.rna.tf32.f32 %0, %1;" : "=r"(u) : "f"(f)); return u;
}
__device__ __forceinline__ void mma_tf32(float* d, const uint32_t* a, const uint32_t* b) {
    asm volatile(
        "mma.sync.aligned.m16n8k8.row.col.f32.tf32.tf32.f32 "
        "{%0,%1,%2,%3}, {%4,%5,%6,%7}, {%8,%9}, {%0,%1,%2,%3};"
        : "+f"(d[0]), "+f"(d[1]), "+f"(d[2]), "+f"(d[3])
        : "r"(a[0]), "r"(a[1]), "r"(a[2]), "r"(a[3]), "r"(b[0]), "r"(b[1]));
}

// 8-CTA group barrier (per batch-group), generation counter survives replays
__device__ __forceinline__ void group_sync(int grp) {
    __syncthreads();
    if (threadIdx.x == 0) {
        __threadfence();
        int gen = g_geng[grp];
        if (atomicAdd(&g_cntg[grp], 1) == 7) {
            g_cntg[grp] = 0;
            __threadfence();
            g_geng[grp] = gen + 1;
        } else {
            while (g_geng[grp] == gen) { __nanosleep(32); }
            __threadfence();
        }
    }
    __syncthreads();
}

// ---------------- weight reordering: W'[3j+g] = W[g*H + j] -----------------
__global__ void reorder_kernel(const float* __restrict__ Wx0, const float* __restrict__ bx0,
                               const float* __restrict__ Wh0, const float* __restrict__ bh0,
                               const float* __restrict__ Wx1, const float* __restrict__ bx1,
                               const float* __restrict__ Wh1, const float* __restrict__ bh1) {
    int tid = blockIdx.x * blockDim.x + threadIdx.x;
    int stride = gridDim.x * blockDim.x;
    for (int idx = tid; idx < G3 * DIN; idx += stride) {
        int n = idx / DIN, k = idx % DIN;
        int j = n / 3, g = n % 3;
        g_Wx0t[idx] = cvt_tf32(Wx0[(g * HH + j) * DIN + k]);
    }
    for (int idx = tid; idx < G3 * HH; idx += stride) {
        int n = idx / HH, k = idx % HH;
        int j = n / 3, g = n % 3;
        int s = (g * HH + j) * HH + k;
        g_Wh0p[idx] = Wh0[s];
        g_Wx1t[idx] = cvt_tf32(Wx1[s]);
        g_Wh1p[idx] = Wh1[s];
    }
    for (int idx = tid; idx < G3; idx += stride) {
        int j = idx / 3, g = idx % 3;
        g_bx0p[idx] = bx0[g * HH + j];
        g_bh0p[idx] = bh0[g * HH + j];
        g_bx1p[idx] = bx1[g * HH + j];
        g_bh1p[idx] = bh1[g * HH + j];
    }
}

// ---------------- tf32 mma.sync x-gates GEMM (proven 385us version) --------
// CTA tile 128x128, 8 warps (2x4), warp tile 64x32, kc=32 double-buffered.
// XS=36: conflict-free LDS.32 fragments AND conflict-free STS.128 fills.
#define XS 36
#define XG_SMEM (2 * 2 * 128 * XS * 4)   // 73728 B

__global__ __launch_bounds__(256, 2) void xgates_mma(const float* __restrict__ X,
                                                     const uint32_t* __restrict__ Wt,
                                                     const float* __restrict__ bp,
                                                     float* __restrict__ C, int K) {
    extern __shared__ uint32_t sm[];
    uint32_t* As = sm;                  // [2][128*XS]
    uint32_t* Bs = sm + 2 * 128 * XS;   // [2][128*XS]

    const int tid = threadIdx.x;
    const int wid = tid >> 5, lane = tid & 31;
    const int g = lane >> 2, t = lane & 3;
    const int warp_m = wid & 1, warp_n = wid >> 1;
    const int m0 = blockIdx.y * 128, n0 = blockIdx.x * 128;
    const int nc = K >> 5;

    float acc[4][4][4];
#pragma unroll
    for (int mt = 0; mt < 4; mt++)
#pragma unroll
        for (int nt = 0; nt < 4; nt++)
#pragma unroll
            for (int r = 0; r < 4; r++) acc[mt][nt][r] = 0.0f;

    uint4 ra[4], rb[4];

    auto ldg_chunk = [&](int c) {
#pragma unroll
        for (int q = 0; q < 4; q++) {
            int idx = tid + q * 256;
            int row = idx >> 3;
            int kq = (idx & 7) * 4;
            const float4 xv = *(const float4*)&X[(size_t)(m0 + row) * K + c * 32 + kq];
            ra[q].x = cvt_tf32(xv.x); ra[q].y = cvt_tf32(xv.y);
            ra[q].z = cvt_tf32(xv.z); ra[q].w = cvt_tf32(xv.w);
            rb[q] = *(const uint4*)&Wt[(size_t)(n0 + row) * K + c * 32 + kq];
        }
    };
    auto sts_chunk = [&](int buf) {
#pragma unroll
        for (int q = 0; q < 4; q++) {
            int idx = tid + q * 256;
            int row = idx >> 3;
            int kq = (idx & 7) * 4;
            *(uint4*)&As[buf * 128 * XS + row * XS + kq] = ra[q];
            *(uint4*)&Bs[buf * 128 * XS + row * XS + kq] = rb[q];
        }
    };

    ldg_chunk(0);
    sts_chunk(0);
    __syncthreads();

    int buf = 0;
    for (int c = 0; c < nc; c++) {
        if (c + 1 < nc) ldg_chunk(c + 1);

        const uint32_t* Ab = As + buf * 128 * XS;
        const uint32_t* Bb = Bs + buf * 128 * XS;
#pragma unroll
        for (int ks = 0; ks < 4; ks++) {
            const int k0 = ks * 8;
            uint32_t a[4][4], b[4][2];
#pragma unroll
            for (int mt = 0; mt < 4; mt++) {
                int r0 = warp_m * 64 + mt * 16;
                a[mt][0] = Ab[(r0 + g) * XS + k0 + t];
                a[mt][1] = Ab[(r0 + g + 8) * XS + k0 + t];
                a[mt][2] = Ab[(r0 + g) * XS + k0 + t + 4];
                a[mt][3] = Ab[(r0 + g + 8) * XS + k0 + t + 4];
            }
#pragma unroll
            for (int nt = 0; nt < 4; nt++) {
                int c0 = warp_n * 32 + nt * 8;
                b[nt][0] = Bb[(c0 + g) * XS + k0 + t];
                b[nt][1] = Bb[(c0 + g) * XS + k0 + t + 4];
            }
#pragma unroll
            for (int mt = 0; mt < 4; mt++)
#pragma unroll
                for (int nt = 0; nt < 4; nt++)
                    mma_tf32(acc[mt][nt], a[mt], b[nt]);
        }

        if (c + 1 < nc) sts_chunk(buf ^ 1);
        __syncthreads();
        buf ^= 1;
    }

    float bb0[4], bb1[4];
#pragma unroll
    for (int nt = 0; nt < 4; nt++) {
        int col = n0 + warp_n * 32 + nt * 8 + 2 * t;
        bb0[nt] = bp[col];
        bb1[nt] = bp[col + 1];
    }
#pragma unroll
    for (int mt = 0; mt < 4; mt++) {
        int r0 = m0 + warp_m * 64 + mt * 16;
#pragma unroll
        for (int nt = 0; nt < 4; nt++) {
            int col = n0 + warp_n * 32 + nt * 8 + 2 * t;
            float2 v0 = make_float2(acc[mt][nt][0] + bb0[nt], acc[mt][nt][1] + bb1[nt]);
            float2 v1 = make_float2(acc[mt][nt][2] + bb0[nt], acc[mt][nt][3] + bb1[nt]);
            *(float2*)&C[(size_t)(r0 + g) * G3 + col] = v0;
            *(float2*)&C[(size_t)(r0 + g + 8) * G3 + col] = v1;
        }
    }
}

// ---------------- persistent recurrent kernel: tf32 mma.sync ---------------
// Grid 8x16 = 128 CTAs, 256 threads.  Full 64x256 h tile per step (proven
// R8 layout, conflict-free), + register-resident h_prev and ks+1 fragment
// register double-buffering (LDS.32, layout-neutral).
#define RWS 260                 // Ws stride: (4g+t) banks distinct
#define RAS 260                 // As stride (full 256-col tile)
#define RGS 100                 // Gs stride
#define SMEM_REC2 ((96 * RWS + 64 * RAS + 64 * RGS) * 4)   // 192000 B

__global__ __launch_bounds__(256) void recurrent_mma(
    const float* __restrict__ xg, const float* __restrict__ Whp,
    const float* __restrict__ bhp, const float* __restrict__ h0,
    const float* __restrict__ gamma, const float* __restrict__ beta,
    float* __restrict__ out_seq, float* __restrict__ final_h) {
    extern __shared__ uint32_t sm2[];
    uint32_t* Ws = sm2;                        // [96][RWS] tf32 Wh'
    uint32_t* As = sm2 + 96 * RWS;             // [64][RAS] tf32 full h tile
    float*    Gs = (float*)(sm2 + 96 * RWS + 64 * RAS);  // [64][RGS] h_gates

    const int tid = threadIdx.x;
    const int wid = tid >> 5, lane = tid & 31;
    const int g = lane >> 2, t = lane & 3;
    const int warp_m = wid & 1, warp_n = wid >> 1;
    const int n0 = blockIdx.x * 96;
    const int b0 = blockIdx.y * 64;
    const int grp = blockIdx.y;
    const int tx = tid & 15, ty = tid >> 4;
    const int c0 = 6 * tx;
    const int j0 = n0 / 3 + 2 * tx;

    // one-time: Wh' (gate-interleaved [n][k]) -> tf32 smem
    for (int idx = tid; idx < 96 * 256; idx += 256) {
        int n = idx >> 8, k = idx & 255;
        Ws[n * RWS + k] = cvt_tf32(Whp[(size_t)(n0 + n) * HH + k]);
    }

    float bias[6];
#pragma unroll
    for (int v = 0; v < 6; v++) bias[v] = bhp[n0 + c0 + v];

    float gm[4][2], bt[4][2], h_prev[4][2];
#pragma unroll
    for (int i = 0; i < 4; i++) {
        int b = b0 + ty * 4 + i;
#pragma unroll
        for (int u = 0; u < 2; u++) {
            gm[i][u] = gamma[b * HH + j0 + u];
            bt[i][u] = beta [b * HH + j0 + u];
            h_prev[i][u] = h0[b * HH + j0 + u];
        }
    }

    {   // init hidden state
        int jb = n0 / 3;
        for (int idx = tid; idx < 64 * 32; idx += 256) {
            int rr = idx >> 5, cc = idx & 31;
            int off = (b0 + rr) * HH + jb + cc;
            g_hbuf[0][off] = h0[off];
        }
    }
    group_sync(grp);

    for (int step = 0; step < TT; step++) {
        const float* hcur = g_hbuf[step & 1];
        float* hnext = g_hbuf[(step + 1) & 1];

        // ---- load full h tile: 2 waves x 8 ldcv float4 per thread ----
#pragma unroll
        for (int w = 0; w < 2; w++) {
            float4 buf[8];
#pragma unroll
            for (int p = 0; p < 8; p++) {
                int idx = (w * 8 + p) * 256 + tid;
                int row = idx >> 6, kq = (idx & 63) * 4;
                buf[p] = __ldcv((const float4*)&hcur[(size_t)(b0 + row) * HH + kq]);
            }
#pragma unroll
            for (int p = 0; p < 8; p++) {
                int idx = (w * 8 + p) * 256 + tid;
                int row = idx >> 6, kq = (idx & 63) * 4;
                uint4 cv;
                cv.x = cvt_tf32(buf[p].x); cv.y = cvt_tf32(buf[p].y);
                cv.z = cvt_tf32(buf[p].z); cv.w = cvt_tf32(buf[p].w);
                *(uint4*)&As[row * RAS + kq] = cv;
            }
        }
        __syncthreads();

        // ---- GEMM: LDS.32 fragments, ks+1 register double-buffer ----
        float acc[2][3][4];
#pragma unroll
        for (int mt = 0; mt < 2; mt++)
#pragma unroll
            for (int nt = 0; nt < 3; nt++)
#pragma unroll
                for (int r = 0; r < 4; r++) acc[mt][nt][r] = 0.0f;

        uint32_t ac[2][4], bc[3][2], an[2][4], bn[3][2];
        auto ldfrag = [&](int k0, uint32_t A[2][4], uint32_t B[3][2]) {
#pragma unroll
            for (int mt = 0; mt < 2; mt++) {
                int r0 = warp_m * 32 + mt * 16;
                A[mt][0] = As[(r0 + g) * RAS + k0 + t];
                A[mt][1] = As[(r0 + g + 8) * RAS + k0 + t];
                A[mt][2] = As[(r0 + g) * RAS + k0 + t + 4];
                A[mt][3] = As[(r0 + g + 8) * RAS + k0 + t + 4];
            }
#pragma unroll
            for (int nt = 0; nt < 3; nt++) {
                int cb = warp_n * 24 + nt * 8;
                B[nt][0] = Ws[(cb + g) * RWS + k0 + t];
                B[nt][1] = Ws[(cb + g) * RWS + k0 + t + 4];
            }
        };

        ldfrag(0, ac, bc);
#pragma unroll
        for (int ks = 0; ks < 32; ks++) {
            if (ks < 31) ldfrag((ks + 1) * 8, an, bn);
#pragma unroll
            for (int mt = 0; mt < 2; mt++)
#pragma unroll
                for (int nt = 0; nt < 3; nt++)
                    mma_tf32(acc[mt][nt], ac[mt], bc[nt]);
#pragma unroll
            for (int mt = 0; mt < 2; mt++)
#pragma unroll
                for (int r = 0; r < 4; r++) ac[mt][r] = an[mt][r];
#pragma unroll
            for (int nt = 0; nt < 3; nt++) {
                bc[nt][0] = bn[nt][0]; bc[nt][1] = bn[nt][1];
            }
        }

        // stage h_gates to smem (decouple MMA fragment layout from gate math)
#pragma unroll
        for (int mt = 0; mt < 2; mt++) {
            int row = warp_m * 32 + mt * 16 + g;
#pragma unroll
            for (int nt = 0; nt < 3; nt++) {
                int col = warp_n * 24 + nt * 8 + 2 * t;
                *(float2*)&Gs[row * RGS + col] =
                    make_float2(acc[mt][nt][0], acc[mt][nt][1]);
                *(float2*)&Gs[(row + 8) * RGS + col] =
                    make_float2(acc[mt][nt][2], acc[mt][nt][3]);
            }
        }
        __syncthreads();

        // gates + FiLM + writes (h_prev register-resident)
#pragma unroll
        for (int i = 0; i < 4; i++) {
            int b = b0 + ty * 4 + i;
            int rl = ty * 4 + i;
            const float* xgp = xg + ((size_t)step * BB + b) * G3 + n0 + c0;
            const float* gr = &Gs[rl * RGS + c0];
            float hv[2];
#pragma unroll
            for (int u = 0; u < 2; u++) {
                float z  = sigm_f(xgp[3 * u + 0] + gr[3 * u + 0] + bias[3 * u + 0]);
                float rr = sigm_f(xgp[3 * u + 1] + gr[3 * u + 1] + bias[3 * u + 1]);
                float nn = tanh_f(xgp[3 * u + 2] + rr * (gr[3 * u + 2] + bias[3 * u + 2]));
                float hp = h_prev[i][u];
                float h  = nn + z * (hp - nn);
                hv[u] = fmaf(gm[i][u], h, bt[i][u]);
                h_prev[i][u] = hv[u];
            }
            float2 hv2 = make_float2(hv[0], hv[1]);
            *(float2*)&hnext[(size_t)b * HH + j0] = hv2;
            *(float2*)&out_seq[((size_t)step * BB + b) * HH + j0] = hv2;
            if (step == TT - 1)
                *(float2*)&final_h[(size_t)b * HH + j0] = hv2;
        }
        group_sync(grp);
    }
}

// ---------------- host launcher -------------------------------------------
extern "C" void kernel_launch(void* const* d_in, const int* in_sizes, int n_in,
                              void* d_out, int out_size) {
    (void)in_sizes; (void)n_in; (void)out_size;
    const float* x      = (const float*)d_in[0];
    const float* init_s = (const float*)d_in[1];
    const float* gammas = (const float*)d_in[2];
    const float* betas  = (const float*)d_in[3];
    const float* Wx0 = (const float*)d_in[4];
    const float* bx0 = (const float*)d_in[5];
    const float* Wh0 = (const float*)d_in[6];
    const float* bh0 = (const float*)d_in[7];
    const float* Wx1 = (const float*)d_in[8];
    const float* bx1 = (const float*)d_in[9];
    const float* Wh1 = (const float*)d_in[10];
    const float* bh1 = (const float*)d_in[11];
    float* out = (float*)d_out;

    uint32_t *pWx0t, *pWx1t;
    float *pWh0p, *pWh1p, *pbx0p, *pbh0p, *pbx1p, *pbh1p, *pxg, *pout0;
    cudaGetSymbolAddress((void**)&pWx0t, g_Wx0t);
    cudaGetSymbolAddress((void**)&pWx1t, g_Wx1t);
    cudaGetSymbolAddress((void**)&pWh0p, g_Wh0p);
    cudaGetSymbolAddress((void**)&pWh1p, g_Wh1p);
    cudaGetSymbolAddress((void**)&pbx0p, g_bx0p);
    cudaGetSymbolAddress((void**)&pbh0p, g_bh0p);
    cudaGetSymbolAddress((void**)&pbx1p, g_bx1p);
    cudaGetSymbolAddress((void**)&pbh1p, g_bh1p);
    cudaGetSymbolAddress((void**)&pxg,   g_xg);
    cudaGetSymbolAddress((void**)&pout0, g_out0);

    cudaFuncSetAttribute(recurrent_mma,
                         cudaFuncAttributeMaxDynamicSharedMemorySize, SMEM_REC2);
    cudaFuncSetAttribute(xgates_mma,
                         cudaFuncAttributeMaxDynamicSharedMemorySize, XG_SMEM);

    const size_t out1_elems = (size_t)TT * BB * HH;

    reorder_kernel<<<768, 256>>>(Wx0, bx0, Wh0, bh0, Wx1, bx1, Wh1, bh1);

    // layer 0
    xgates_mma<<<dim3(6, 1024), 256, XG_SMEM>>>(x, pWx0t, pbx0p, pxg, DIN);
    recurrent_mma<<<dim3(8, 16), 256, SMEM_REC2>>>(
        pxg, pWh0p, pbh0p, init_s, gammas, betas,
        pout0, out + out1_elems);

    // layer 1
    xgates_mma<<<dim3(6, 1024), 256, XG_SMEM>>>(pout0, pWx1t, pbx1p, pxg, HH);
    recurrent_mma<<<dim3(8, 16), 256, SMEM_REC2>>>(
        pxg, pWh1p, pbh1p, init_s + BB * HH,
        gammas + (size_t)BB * HH, betas + (size_t)BB * HH,
        out, out + out1_elems + (size_t)BB * HH);
}